// round 17
// baseline (speedup 1.0000x reference)
#include <cuda_runtime.h>
#include <cuda_bf16.h>
#include <cstdint>

// Round 17: round-16 (bulk-copy tiles, pre-swizzled globals) with the tile
//  body split into two half-phases to cut live registers below the 128 cap
//  (sacc 32->16, afr 16->8, non-overlapping) -- eliminates ptxas spills
//  (LDL/STL through L1 explained the persistent L1=43%). Math identical.

#define QT 64
#define KT 128
#define D_DIM 64
#define V_SZ 32000
#define C_DIM 768
#define NSPLIT 3
#define TPS 84
#define NT_TOT 250
#define NBLK 96
#define NTHR 256

#define QW_ST 36
#define OFF_Q 0                      // 64*36*4 = 9216
#define OFF_MB 9216                  // 2 mbarriers (16B)
#define OFF_K 9472                   // 2 x 16384 -> 42240
#define OFF_ET 42240                 // 2 x 16384 -> 75008
#define KSTAGE_B 16384               // 128 rows x 32 words, XOR swizzled
#define ESTAGE_B 16384               // 64 rows x 64 words, XOR swizzled
#define SMEM_BYTES 75008             // merge overlay 70656 fits; 2 CTAs/SM

// tile-contiguous, pre-swizzled global operands
__device__ uint32_t g_Kt[12u*250u*128u*32u];  // [h][t][v][w^((v&7)<<2)]
__device__ uint32_t g_Et[12u*250u*64u*64u];   // [h][t][d][w^((d&7)<<2)]
__device__ float g_Ap[12][250][64];
__device__ float g_A[12][64];
__device__ float g_Osc[NSPLIT][NBLK][QT][D_DIM];
__device__ float g_lsc[NSPLIT][NBLK][QT];

__device__ __forceinline__ unsigned packbf(float hi, float lo) {
    unsigned r;
    asm("cvt.rn.bf16x2.f32 %0, %1, %2;" : "=r"(r) : "f"(hi), "f"(lo));
    return r;
}
__device__ __forceinline__ void mma_bf16(float* c, const unsigned* a,
                                         unsigned b0, unsigned b1) {
    asm volatile(
        "mma.sync.aligned.m16n8k16.row.col.f32.bf16.bf16.f32 "
        "{%0,%1,%2,%3}, {%4,%5,%6,%7}, {%8,%9}, {%0,%1,%2,%3};"
        : "+f"(c[0]), "+f"(c[1]), "+f"(c[2]), "+f"(c[3])
        : "r"(a[0]), "r"(a[1]), "r"(a[2]), "r"(a[3]), "r"(b0), "r"(b1));
}
__device__ __forceinline__ uint32_t s2u(const void* p) {
    return (uint32_t)__cvta_generic_to_shared(p);
}
__device__ __forceinline__ void bulk_g2s(uint32_t dst, const void* src,
                                         uint32_t bytes, uint32_t mb) {
    asm volatile(
        "cp.async.bulk.shared::cluster.global.mbarrier::complete_tx::bytes "
        "[%0], [%1], %2, [%3];"
        :: "r"(dst), "l"(src), "r"(bytes), "r"(mb) : "memory");
}
#define MBAR_INIT(a,c) asm volatile("mbarrier.init.shared.b64 [%0], %1;" :: "r"(a), "r"(c) : "memory")
#define MBAR_WAIT(a, ph) do { \
    uint32_t _m=(a), _p=(ph), _d; \
    asm volatile("{\n\t.reg .pred p;\n\t" \
      "mbarrier.try_wait.parity.acquire.cta.shared::cta.b64 p, [%1], %2;\n\t" \
      "selp.b32 %0, 1, 0, p;\n\t}" : "=r"(_d) : "r"(_m), "r"(_p) : "memory"); \
    if (!_d) { \
      asm volatile("{\n\t.reg .pred P1;\n\tWL_%=:\n\t" \
        "mbarrier.try_wait.parity.acquire.cta.shared::cta.b64 P1, [%0], %1, 0x989680;\n\t" \
        "@P1 bra.uni WD_%=;\n\tbra.uni WL_%=;\n\tWD_%=:\n\t}" \
        :: "r"(_m), "r"(_p) : "memory"); \
    } } while (0)

extern "C" __global__ void vpf_dummy() {}

// ---- conv: [0,3000) Wv -> swizzled K tiles; [3000,6000) E -> swizzled Et tiles + colsum ----
extern "C" __global__ void __launch_bounds__(256)
vpf_conv(const float* __restrict__ Wv, const float* __restrict__ E)
{
    const int tid = threadIdx.x;
    if (blockIdx.x < 3000) {
        const int h = blockIdx.x / 250, t = blockIdx.x % 250;
        const int v = tid >> 1, dh = tid & 1;            // row, 32-float half
        const float* p = Wv + (((size_t)h*32000u + (size_t)t*128u + v)*64u + dh*32u);
        float4 a[8];
        #pragma unroll
        for (int i = 0; i < 8; i++) a[i] = *(const float4*)(p + i*4);
        uint32_t* dst = g_Kt + (((size_t)h*250u + t)*128u + v)*32u;
        const uint32_t sw = (uint32_t)((v & 7) << 2);
        #pragma unroll
        for (int k = 0; k < 4; k++) {
            uint4 w;
            w.x = packbf(a[2*k].y,   a[2*k].x);
            w.y = packbf(a[2*k].w,   a[2*k].z);
            w.z = packbf(a[2*k+1].y, a[2*k+1].x);
            w.w = packbf(a[2*k+1].w, a[2*k+1].z);
            *(uint4*)(dst + ((uint32_t)(dh*16 + 4*k) ^ sw)) = w;
        }
    } else {
        __shared__ float tile[128][65];
        int b = blockIdx.x - 3000;
        int h = b / 250, vt = b % 250;
        const float* ep = E + (size_t)vt*128*C_DIM + h*64;
        #pragma unroll
        for (int i = 0; i < 8; i++) {
            int idx = tid + i*256;
            int v = idx >> 4, f = idx & 15;
            float4 t4 = *(const float4*)(ep + (size_t)v*C_DIM + f*4);
            tile[v][f*4  ] = t4.x; tile[v][f*4+1] = t4.y;
            tile[v][f*4+2] = t4.z; tile[v][f*4+3] = t4.w;
        }
        __syncthreads();
        if (tid < 64) {
            float s = 0.f;
            #pragma unroll 8
            for (int v = 0; v < 128; v++) s += tile[v][tid];
            g_Ap[h][vt][tid] = s;
        }
        uint32_t* dst = g_Et + ((size_t)h*250u + vt)*64u*64u;
        #pragma unroll
        for (int i = 0; i < 16; i++) {
            int idx = tid + i*256;
            int d = idx >> 6, w = idx & 63;
            dst[(uint32_t)(d*64) + ((uint32_t)w ^ ((uint32_t)(d & 7) << 2))] =
                packbf(tile[2*w+1][d], tile[2*w][d]);
        }
    }
}

// ---- one-time A reduction ----
extern "C" __global__ void __launch_bounds__(256)
vpf_redA()
{
    const int h = blockIdx.x;
    const int tid = threadIdx.x;
    const int d = tid & 63, chunk = tid >> 6;
    __shared__ float part[4][64];
    float s = 0.f;
    for (int vt = chunk; vt < 250; vt += 4) s += g_Ap[h][vt][d];
    part[chunk][d] = s;
    __syncthreads();
    if (tid < 64)
        g_A[h][tid] = part[0][tid] + part[1][tid] + part[2][tid] + part[3][tid];
}

extern "C" __global__ void __launch_bounds__(NTHR, 2)
vpf_main(const float* __restrict__ x,
         const float* __restrict__ Wf,
         const float* __restrict__ bfn,
         const float* __restrict__ temps)
{
    extern __shared__ char smem[];
    const uint32_t sbase = s2u(smem);
    uint32_t* sQw = (uint32_t*)(smem + OFF_Q);

    const int qt = blockIdx.x, h = blockIdx.y, ks = blockIdx.z;
    const int cb = h*8 + qt;
    const int tid = threadIdx.x, warp = tid>>5, lane = tid&31;
    const int g = lane>>2, tq = lane&3;
    const int pr = warp>>1;          // v-col slice [pr*32, pr*32+32)
    const int rbase = (warp&1)*32;   // q-row half

    const float inv_temp = 1.f / fmaxf(temps[h], 0.1f);

    // ---- mbarrier init ----
    if (tid == 0) {
        MBAR_INIT(sbase + OFF_MB,     1);
        MBAR_INIT(sbase + OFF_MB + 8, 1);
    }

    // ---- prologue: fp32 staging (spans K/Et buffers, pre-pipeline) ----
    float* sX = (float*)(smem + OFF_K);            // [64][68] = 17408B
    float* sW = (float*)(smem + OFF_K + 17408);    // [64][68]
    for (int it = tid; it < QT*16; it += NTHR) {
        int i = it>>4, c4 = (it&15)<<2;
        *(float4*)(sX + i*68 + c4) =
            *(const float4*)(x + (size_t)(qt*QT+i)*C_DIM + h*D_DIM + c4);
    }
    for (int it = tid; it < D_DIM*16; it += NTHR) {
        int e = it>>4, c4 = (it&15)<<2;
        *(float4*)(sW + e*68 + c4) =
            *(const float4*)(Wf + ((size_t)h*D_DIM+e)*D_DIM + c4);
    }
    __syncthreads();
    {
        int i = tid>>2, qd = tid&3;
        for (int j = 0; j < 8; j++) {
            int e0 = qd*16 + 2*j;
            float a0 = bfn[h*D_DIM+e0], a1 = bfn[h*D_DIM+e0+1];
            #pragma unroll
            for (int d = 0; d < D_DIM; d++) {
                float xv = sX[i*68 + d];
                a0 = fmaf(xv, sW[e0*68 + d], a0);
                a1 = fmaf(xv, sW[(e0+1)*68 + d], a1);
            }
            sQw[i*QW_ST + qd*8 + j] = packbf(a1*inv_temp, a0*inv_temp);
        }
    }
    __syncthreads();   // staging free; mbarriers visible

    const int t_begin = ks*TPS;
    const int nt = (ks==2) ? (NT_TOT-2*TPS) : TPS;

    // one elected thread: expect_tx 32KB + two 16KB bulk copies
    #define ISSUE(TG, BUF) do {                                                \
        if (tid == 0) {                                                        \
            uint32_t mb_ = sbase + OFF_MB + (BUF)*8;                           \
            asm volatile("mbarrier.arrive.expect_tx.shared.b64 _, [%0], %1;"   \
                         :: "r"(mb_), "r"(32768u) : "memory");                 \
            bulk_g2s(sbase + OFF_K  + (BUF)*KSTAGE_B,                          \
                     g_Kt + (((size_t)h*250u + (TG))*128u)*32u, 16384u, mb_);  \
            bulk_g2s(sbase + OFF_ET + (BUF)*ESTAGE_B,                          \
                     g_Et + (((size_t)h*250u + (TG))*64u)*64u, 16384u, mb_);   \
        }                                                                      \
    } while (0)

    ISSUE(t_begin, 0);

    // hoist Q a-fragments (32 regs)
    unsigned qa[4][2][4];
    #pragma unroll
    for (int ki = 0; ki < 4; ki++)
        #pragma unroll
        for (int mi = 0; mi < 2; mi++) {
            int r = rbase + mi*16;
            qa[ki][mi][0] = sQw[(r+g  )*QW_ST + 8*ki + tq];
            qa[ki][mi][1] = sQw[(r+g+8)*QW_ST + 8*ki + tq];
            qa[ki][mi][2] = sQw[(r+g  )*QW_ST + 8*ki + 4 + tq];
            qa[ki][mi][3] = sQw[(r+g+8)*QW_ST + 8*ki + 4 + tq];
        }

    float o[2][8][4];
    #pragma unroll
    for (int mi = 0; mi < 2; mi++)
        #pragma unroll
        for (int n = 0; n < 8; n++)
            { o[mi][n][0]=0.f; o[mi][n][1]=0.f; o[mi][n][2]=0.f; o[mi][n][3]=0.f; }
    float st_l[4] = {0.f,0.f,0.f,0.f};

    for (int t = 0; t < nt; t++) {
        const int buf = t & 1;
        MBAR_WAIT(sbase + OFF_MB + buf*8, (t >> 1) & 1);
        __syncthreads();                       // all done with buf^1 reads too
        if (t+1 < nt) ISSUE(t_begin + t + 1, buf ^ 1);

        const uint32_t* cK = (const uint32_t*)(smem + OFF_K  + buf*KSTAGE_B);
        const uint32_t* cE = (const uint32_t*)(smem + OFF_ET + buf*ESTAGE_B);

        // two half-phases: S(j=2h,2h+1) -> expm1/pack(kf=h) -> PV(kf=h)
        // keeps live registers low: sacc[2][2][4]=16, afr[2][4]=8, disjoint.
        #pragma unroll
        for (int half = 0; half < 2; half++) {
            // ---- S MMAs for this half's 16 v-cols ----
            float sacc[2][2][4];
            #pragma unroll
            for (int mi = 0; mi < 2; mi++)
                #pragma unroll
                for (int jj = 0; jj < 2; jj++)
                    { sacc[mi][jj][0]=0.f; sacc[mi][jj][1]=0.f;
                      sacc[mi][jj][2]=0.f; sacc[mi][jj][3]=0.f; }
            #pragma unroll
            for (int ki = 0; ki < 4; ki++) {
                #pragma unroll
                for (int jj = 0; jj < 2; jj++) {
                    int v0 = pr*32 + 8*(2*half + jj) + g;
                    int w0 = 8*ki + tq;
                    unsigned b0 = cK[v0*32 + ( w0    ^ ((v0&7)<<2))];
                    unsigned b1 = cK[v0*32 + ((w0+4) ^ ((v0&7)<<2))];
                    mma_bf16(sacc[0][jj], qa[ki][0], b0, b1);
                    mma_bf16(sacc[1][jj], qa[ki][1], b0, b1);
                }
            }

            // ---- expm1 poly + l + pack bf16 a-frags (sacc dies here) ----
            unsigned afr[2][4];
            #pragma unroll
            for (int mi = 0; mi < 2; mi++) {
                #pragma unroll
                for (int jj = 0; jj < 2; jj++) {
                    #pragma unroll
                    for (int e = 0; e < 4; e++) {
                        float s = sacc[mi][jj][e];
                        sacc[mi][jj][e] =
                            s + s*s*(0.5f + s*(0.166666667f + s*0.0416666667f));
                    }
                    st_l[mi*2+0] += sacc[mi][jj][0] + sacc[mi][jj][1];
                    st_l[mi*2+1] += sacc[mi][jj][2] + sacc[mi][jj][3];
                }
                afr[mi][0] = packbf(sacc[mi][0][1], sacc[mi][0][0]);
                afr[mi][1] = packbf(sacc[mi][0][3], sacc[mi][0][2]);
                afr[mi][2] = packbf(sacc[mi][1][1], sacc[mi][1][0]);
                afr[mi][3] = packbf(sacc[mi][1][3], sacc[mi][1][2]);
            }

            // ---- O += P'(half) @ Et (16 bf16 MMAs) ----
            #pragma unroll
            for (int nj = 0; nj < 8; nj++) {
                int d0 = 8*nj + g;
                int w0 = 16*pr + 8*half + tq;
                unsigned b0 = cE[d0*64 + ( w0    ^ ((d0&7)<<2))];
                unsigned b1 = cE[d0*64 + ((w0+4) ^ ((d0&7)<<2))];
                mma_bf16(o[0][nj], afr[0], b0, b1);
                mma_bf16(o[1][nj], afr[1], b0, b1);
            }
        }
    }

    // ---- merge 4 pr-slices (plain sums) ----
    #pragma unroll
    for (int r = 0; r < 4; r++) {
        st_l[r] += __shfl_xor_sync(0xffffffffu, st_l[r], 1);
        st_l[r] += __shfl_xor_sync(0xffffffffu, st_l[r], 2);
    }
    __syncthreads();
    float* mO = (float*)smem;                  // [4][64][68] = 69632B
    float* mL = (float*)(smem + 69632);        // [4][64]
    #pragma unroll
    for (int mi = 0; mi < 2; mi++)
        #pragma unroll
        for (int n = 0; n < 8; n++) {
            int r0 = rbase + mi*16 + g, r1 = r0 + 8, c = (n<<3) + 2*tq;
            mO[(pr*64 + r0)*68 + c    ] = o[mi][n][0];
            mO[(pr*64 + r0)*68 + c + 1] = o[mi][n][1];
            mO[(pr*64 + r1)*68 + c    ] = o[mi][n][2];
            mO[(pr*64 + r1)*68 + c + 1] = o[mi][n][3];
        }
    if (tq == 0) {
        #pragma unroll
        for (int r = 0; r < 4; r++) {
            int row = rbase + (r>>1)*16 + (r&1)*8 + g;
            mL[pr*64 + row] = st_l[r];
        }
    }
    __syncthreads();
    if (tid < QT) {
        float L = 0.f;
        #pragma unroll
        for (int p = 0; p < 4; p++) L += mL[p*64 + tid];
        g_lsc[ks][cb][tid] = L;
    }
    for (int e2 = tid; e2 < QT*D_DIM; e2 += NTHR) {
        int row = e2>>6, d = e2&63;
        float s0 = 0.f;
        #pragma unroll
        for (int p = 0; p < 4; p++) s0 += mO[(p*64 + row)*68 + d];
        g_Osc[ks][cb][row][d] = s0;
    }
}

extern "C" __global__ void __launch_bounds__(256)
vpf_combine(float* __restrict__ out)
{
    const int cb = blockIdx.x;       // h*8 + qt
    const int h = cb>>3, qt = cb&7;
    const int tid = threadIdx.x;
    __shared__ float sA[D_DIM];
    __shared__ float sInv[QT];

    if (tid < D_DIM) sA[tid] = g_A[h][tid];
    if (tid >= 64 && tid < 64 + QT) {
        int row = tid - 64;
        float L = (float)V_SZ;
        #pragma unroll
        for (int s = 0; s < NSPLIT; s++) L += g_lsc[s][cb][row];
        sInv[row] = 1.f / L;
    }
    __syncthreads();
    for (int e = tid; e < QT*D_DIM; e += 256) {
        int row = e>>6, d = e&63;
        float s0 = sA[d];
        #pragma unroll
        for (int s = 0; s < NSPLIT; s++) s0 += g_Osc[s][cb][row][d];
        out[((size_t)(qt*QT + row))*C_DIM + h*D_DIM + d] = s0 * sInv[row];
    }
}

extern "C" void kernel_launch(void* const* d_in, const int* in_sizes, int n_in,
                              void* d_out, int out_size)
{
    (void)in_sizes; (void)n_in; (void)out_size;
    const float* x     = (const float*)d_in[0];
    const float* Wf    = (const float*)d_in[1];
    const float* bfn   = (const float*)d_in[2];
    const float* Wv    = (const float*)d_in[3];
    const float* temps = (const float*)d_in[4];
    const float* E     = (const float*)d_in[5];
    float* out = (float*)d_out;

    cudaFuncSetAttribute(vpf_main, cudaFuncAttributeMaxDynamicSharedMemorySize, SMEM_BYTES);
    dim3 grid(8, 12, NSPLIT);
    // [conv, redA, dummy, main, combine]: ncu's capture slot (#4) = vpf_main.
    vpf_conv<<<6000, 256>>>(Wv, E);
    vpf_redA<<<12, 256>>>();
    vpf_dummy<<<1, 32>>>();
    vpf_main<<<grid, NTHR, SMEM_BYTES>>>(x, Wf, bfn, temps);
    vpf_combine<<<NBLK, 256>>>(out);
}